// round 2
// baseline (speedup 1.0000x reference)
#include <cuda_runtime.h>
#include <cuda_bf16.h>
#include <math.h>

#define NMAX   100352          // >= 100000, padded
#define EMAX   1300000
#define DIM    64
#define SCAN_B 1024

// ---------------- device scratch ----------------
__device__ int   g_deg[NMAX];
__device__ int   g_cursor[NMAX];
__device__ int   g_off[NMAX];
__device__ int   g_bsum[128];
__device__ float g_dinv[NMAX];
__device__ int   g_col[EMAX];
__device__ int   g_is64;                      // 1 if edge_index is int64, 0 if int32
__device__ float g_h[(size_t)NMAX * DIM];     // pre-scaled features (h * dinv[src])
__device__ float g_agg[(size_t)NMAX * DIM];   // aggregated output of a layer

// ---------------- dtype detection ----------------
// If edge_index is int64 (little-endian) with values < 2^31, every odd 32-bit
// word of the buffer is zero. If int32 (random node ids), they are not.
__global__ void detect_dtype(const unsigned int* __restrict__ w) {
    __shared__ unsigned int acc[256];
    unsigned int v = 0;
    // check odd words of the first 2048 32-bit words (1024 prospective int64s)
    for (int i = threadIdx.x; i < 1024; i += 256) v |= w[2 * i + 1];
    acc[threadIdx.x] = v;
    __syncthreads();
    for (int s = 128; s > 0; s >>= 1) {
        if (threadIdx.x < s) acc[threadIdx.x] |= acc[threadIdx.x + s];
        __syncthreads();
    }
    if (threadIdx.x == 0) g_is64 = (acc[0] == 0) ? 1 : 0;
}

__device__ __forceinline__ int load_idx(const void* ei, long long pos) {
    if (g_is64) return (int)((const long long*)ei)[pos];
    return ((const int*)ei)[pos];
}

// ---------------- CSR build ----------------
__global__ void zero_counts(int n) {
    int i = blockIdx.x * blockDim.x + threadIdx.x;
    if (i < n) { g_deg[i] = 0; g_cursor[i] = 0; }
}

__global__ void count_deg(const void* __restrict__ ei, int E, int n) {
    int e = blockIdx.x * blockDim.x + threadIdx.x;
    if (e < E) {
        int d = load_idx(ei, (long long)E + e);
        if ((unsigned)d < (unsigned)n) atomicAdd(&g_deg[d], 1);
    }
}

// per-block inclusive scan -> exclusive offsets + block sums; also computes dinv
__global__ void scan_block(int n) {
    __shared__ int sh[SCAN_B];
    int i = blockIdx.x * SCAN_B + threadIdx.x;
    int v = (i < n) ? g_deg[i] : 0;
    if (i < n) g_dinv[i] = rsqrtf((float)(v + 1));   // +1 self loop, always > 0
    sh[threadIdx.x] = v;
    __syncthreads();
    #pragma unroll
    for (int s = 1; s < SCAN_B; s <<= 1) {
        int t = (threadIdx.x >= s) ? sh[threadIdx.x - s] : 0;
        __syncthreads();
        sh[threadIdx.x] += t;
        __syncthreads();
    }
    if (i < n) g_off[i] = sh[threadIdx.x] - v;
    if (threadIdx.x == SCAN_B - 1) g_bsum[blockIdx.x] = sh[SCAN_B - 1];
}

__global__ void scan_bsum(int nb) {   // single block of 128
    __shared__ int sh[128];
    int v = (threadIdx.x < nb) ? g_bsum[threadIdx.x] : 0;
    sh[threadIdx.x] = v;
    __syncthreads();
    #pragma unroll
    for (int s = 1; s < 128; s <<= 1) {
        int t = (threadIdx.x >= s) ? sh[threadIdx.x - s] : 0;
        __syncthreads();
        sh[threadIdx.x] += t;
        __syncthreads();
    }
    if (threadIdx.x < nb) g_bsum[threadIdx.x] = sh[threadIdx.x] - v;  // exclusive
}

__global__ void scan_add(int n) {
    int i = blockIdx.x * SCAN_B + threadIdx.x;
    if (i < n) g_off[i] += g_bsum[blockIdx.x];
}

__global__ void fill_csr(const void* __restrict__ ei, int E, int n) {
    int e = blockIdx.x * blockDim.x + threadIdx.x;
    if (e < E) {
        int d = load_idx(ei, (long long)E + e);
        int s = load_idx(ei, e);
        if ((unsigned)d < (unsigned)n && (unsigned)s < (unsigned)n) {
            int p = g_off[d] + atomicAdd(&g_cursor[d], 1);
            g_col[p] = s;
        }
    }
}

// ---------------- GEMM: Y = op(X) @ W, fused epilogues ----------------
// op(X): optional relu.  Epilogue: * scale[row]  (+ postBias[col]).
template<int PRE_RELU>
__global__ __launch_bounds__(256) void gemm64(
    const float* __restrict__ X, const float* __restrict__ W,
    const float* __restrict__ scale,     // per-row, may be null
    const float* __restrict__ postBias,  // per-col, may be null
    float* __restrict__ Y, int n)
{
    __shared__ float Xs[64][68];
    __shared__ float Ws[64][68];
    int tid  = threadIdx.x;
    int row0 = blockIdx.x * 64;

    #pragma unroll 4
    for (int t = tid; t < 64 * 64; t += 256) {
        int r = t >> 6, c = t & 63;
        Ws[r][c] = W[t];
        int gr = row0 + r;
        float v = (gr < n) ? X[(size_t)gr * 64 + c] : 0.f;
        if (PRE_RELU) v = fmaxf(v, 0.f);
        Xs[r][c] = v;
    }
    __syncthreads();

    int ty = tid >> 4, tx = tid & 15;
    int r0 = ty * 4,  c0 = tx * 4;
    float acc[4][4] = {};

    #pragma unroll 16
    for (int k = 0; k < 64; k++) {
        float4 wv = *(const float4*)&Ws[k][c0];
        float x0 = Xs[r0 + 0][k];
        float x1 = Xs[r0 + 1][k];
        float x2 = Xs[r0 + 2][k];
        float x3 = Xs[r0 + 3][k];
        acc[0][0] += x0 * wv.x; acc[0][1] += x0 * wv.y; acc[0][2] += x0 * wv.z; acc[0][3] += x0 * wv.w;
        acc[1][0] += x1 * wv.x; acc[1][1] += x1 * wv.y; acc[1][2] += x1 * wv.z; acc[1][3] += x1 * wv.w;
        acc[2][0] += x2 * wv.x; acc[2][1] += x2 * wv.y; acc[2][2] += x2 * wv.z; acc[2][3] += x2 * wv.w;
        acc[3][0] += x3 * wv.x; acc[3][1] += x3 * wv.y; acc[3][2] += x3 * wv.z; acc[3][3] += x3 * wv.w;
    }

    float4 bv = make_float4(0.f, 0.f, 0.f, 0.f);
    if (postBias) bv = *(const float4*)&postBias[c0];

    #pragma unroll
    for (int i = 0; i < 4; i++) {
        int gr = row0 + r0 + i;
        if (gr < n) {
            float s = scale ? scale[gr] : 1.f;
            float4 o;
            o.x = acc[i][0] * s + bv.x;
            o.y = acc[i][1] * s + bv.y;
            o.z = acc[i][2] * s + bv.z;
            o.w = acc[i][3] * s + bv.w;
            *(float4*)&Y[(size_t)gr * 64 + c0] = o;
        }
    }
}

// ---------------- Gather aggregation: one warp per node ----------------
// out[i] = dinv[i] * ( H[i] + sum_{e: dst=i} H[src_e] ) + bias
// (H already pre-scaled by dinv[src]; self loop = H[i] term)
__global__ __launch_bounds__(256) void gather(
    const float* __restrict__ H, const float* __restrict__ bias,
    float* __restrict__ out, int n)
{
    int warp = (blockIdx.x * blockDim.x + threadIdx.x) >> 5;
    int lane = threadIdx.x & 31;
    if (warp >= n) return;

    int o  = g_off[warp];
    int dg = g_deg[warp];
    const float* Hi = H + (size_t)warp * 64;
    float a0 = Hi[lane];
    float a1 = Hi[lane + 32];

    for (int base = 0; base < dg; base += 32) {
        int m  = min(32, dg - base);
        int sj = (lane < m) ? g_col[o + base + lane] : 0;
        for (int j = 0; j < m; j++) {
            int s = __shfl_sync(0xffffffffu, sj, j);
            const float* Hs = H + (size_t)s * 64;
            a0 += Hs[lane];
            a1 += Hs[lane + 32];
        }
    }
    float di = g_dinv[warp];
    out[(size_t)warp * 64 + lane]      = a0 * di + bias[lane];
    out[(size_t)warp * 64 + lane + 32] = a1 * di + bias[lane + 32];
}

// ---------------- launch ----------------
extern "C" void kernel_launch(void* const* d_in, const int* in_sizes, int n_in,
                              void* d_out, int out_size) {
    const float* x  = (const float*)d_in[0];
    const void*  ei = d_in[1];
    const float* W1 = (const float*)d_in[2];
    const float* b1 = (const float*)d_in[3];
    const float* W2 = (const float*)d_in[4];
    const float* b2 = (const float*)d_in[5];
    const float* Wl = (const float*)d_in[6];
    const float* bl = (const float*)d_in[7];
    float* out = (float*)d_out;

    int n = in_sizes[0] / DIM;          // 100000
    int E = in_sizes[1] / 2;            // 1200000

    float *h, *agg, *dinv;
    cudaGetSymbolAddress((void**)&h,    g_h);
    cudaGetSymbolAddress((void**)&agg,  g_agg);
    cudaGetSymbolAddress((void**)&dinv, g_dinv);

    int nbScan = (n + SCAN_B - 1) / SCAN_B;
    int nbE    = (E + 255) / 256;
    int nbN    = (n + 255) / 256;
    int nbG    = (n * 32 + 255) / 256;       // warp per node
    int nbM    = (n + 63) / 64;

    // CSR build (recomputed every call; deterministic)
    detect_dtype<<<1, 256>>>((const unsigned int*)ei);
    zero_counts<<<nbN, 256>>>(n);
    count_deg<<<nbE, 256>>>(ei, E, n);
    scan_block<<<nbScan, SCAN_B>>>(n);
    scan_bsum<<<1, 128>>>(nbScan);
    scan_add<<<nbScan, SCAN_B>>>(n);
    fill_csr<<<nbE, 256>>>(ei, E, n);

    // layer 1: h = (x @ W1) * dinv ; agg = gather(h)*dinv + b1
    gemm64<0><<<nbM, 256>>>(x, W1, dinv, nullptr, h, n);
    gather<<<nbG, 256>>>(h, b1, agg, n);

    // layer 2: h = (relu(agg) @ W2) * dinv ; agg = gather(h)*dinv + b2
    gemm64<1><<<nbM, 256>>>(agg, W2, dinv, nullptr, h, n);
    gather<<<nbG, 256>>>(h, b2, agg, n);

    // head: out = agg @ Wl + bl
    gemm64<0><<<nbM, 256>>>(agg, Wl, nullptr, bl, out, n);
}